// round 1
// baseline (speedup 1.0000x reference)
#include <cuda_runtime.h>
#include <cuda_bf16.h>

#define N_NODES 100000
#define N_EDGES 1600000
#define HID 64
#define NG 512
#define NCLS 10

// Scratch (device globals -- no allocations allowed)
__device__ float g_h0[N_NODES * HID];
__device__ float g_h1[N_NODES * HID];
__device__ float g_agg[N_NODES * HID];
__device__ int   g_cnt[N_NODES];
__device__ float g_pool[NG * HID];
__device__ int   g_pcnt[NG];

// ---------------------------------------------------------------------------
// Zero counters / pool accumulators
__global__ void k_zero() {
    int i = blockIdx.x * blockDim.x + threadIdx.x;
    if (i < N_NODES) g_cnt[i] = 0;
    if (i < NG * HID) g_pool[i] = 0.f;
    if (i < NG) g_pcnt[i] = 0;
}

// ---------------------------------------------------------------------------
// Embedding lookup: h0 = concat(shape_emb[x[:,0]], color_emb[x[:,1]])
// Also zeroes g_agg and accumulates per-graph node counts.
// 16 threads per node, one float4 each.
__global__ void k_embed(const int* __restrict__ x,
                        const int* __restrict__ batch,
                        const float* __restrict__ semb,
                        const float* __restrict__ cemb) {
    int t = blockIdx.x * blockDim.x + threadIdx.x;   // N_NODES*16 threads
    int node = t >> 4, c4 = t & 15;
    float4 v;
    if (c4 < 8) {
        int s = x[node * 2 + 0];
        v = *(const float4*)&semb[s * 32 + c4 * 4];
    } else {
        int c = x[node * 2 + 1];
        v = *(const float4*)&cemb[c * 32 + (c4 - 8) * 4];
    }
    *(float4*)&g_h0[node * 64 + c4 * 4] = v;
    *(float4*)&g_agg[node * 64 + c4 * 4] = make_float4(0.f, 0.f, 0.f, 0.f);
    if (c4 == 0) atomicAdd(&g_pcnt[batch[node]], 1);
}

// ---------------------------------------------------------------------------
// In-degree count (same for both layers)
__global__ void k_count(const int* __restrict__ ei) {
    int e = blockIdx.x * blockDim.x + threadIdx.x;
    atomicAdd(&g_cnt[ei[N_EDGES + e]], 1);
}

// ---------------------------------------------------------------------------
// Edge scatter: agg[tgt] += h[src].  16 threads/edge, float4 vector atomics.
// layer==0 reads g_h0, layer==1 reads g_h1.
__global__ void k_scatter(const int* __restrict__ ei, int layer) {
    int t = blockIdx.x * blockDim.x + threadIdx.x;   // N_EDGES*16 threads
    int e = t >> 4, c4 = t & 15;
    int s = ei[e];
    int d = ei[N_EDGES + e];
    const float* h = layer ? g_h1 : g_h0;
    float4 v = *(const float4*)&h[s * 64 + c4 * 4];
    atomicAdd((float4*)&g_agg[d * 64 + c4 * 4], v);
}

// ---------------------------------------------------------------------------
// Node update: out = relu( (agg/cnt) @ wl + h @ wr + b )
// Tiled GEMM: 64 nodes x 64 cols per block, 256 threads, 4x4 micro-tiles.
// K is processed in two 64-chunks (chunk0: mean-agg x wl, chunk1: h x wr).
// layer==0: hin=g_h0, writes g_h1.  layer==1: hin=g_h1, pools into g_pool.
// Also resets g_agg to zero for the next scatter pass.
__global__ void __launch_bounds__(256) k_update(
        const float* __restrict__ wl, const float* __restrict__ wr,
        const float* __restrict__ bias, const int* __restrict__ batch,
        int layer) {
    __shared__ float Ws[64][64];    // 16 KB
    __shared__ float XsT[64][64];   // 16 KB  (k-major, node minor)
    __shared__ float invc[64];
    __shared__ float bs[64];

    const float* hin = layer ? g_h1 : g_h0;
    int t  = threadIdx.x;
    int nb = blockIdx.x * 64;
    int nt = t & 15;   // node group (4 nodes)
    int ct = t >> 4;   // col group (4 cols)

    if (t < 64) {
        int n = nb + t;
        float c = 1.f;
        if (n < N_NODES) c = (float)g_cnt[n];
        invc[t] = 1.f / fmaxf(c, 1.f);
        bs[t] = bias[t];
    }

    float4 a0 = make_float4(0.f,0.f,0.f,0.f);
    float4 a1 = a0, a2 = a0, a3 = a0;

    for (int kc = 0; kc < 2; kc++) {
        __syncthreads();
        // load weight chunk (wl for kc=0, wr for kc=1), row-major [k][c]
        const float* w = kc ? wr : wl;
        for (int i = t; i < 1024; i += 256)
            ((float4*)&Ws[0][0])[i] = ((const float4*)w)[i];
        // load input chunk, transposed to [k][node]
        for (int i = t; i < 1024; i += 256) {
            int node = i & 63, kq = i >> 6;     // kq: 0..15 (float4 of k)
            int n = nb + node;
            float4 v = make_float4(0.f,0.f,0.f,0.f);
            if (n < N_NODES) {
                if (kc == 0) {
                    v = *(const float4*)&g_agg[n * 64 + kq * 4];
                    float s = invc[node];
                    v.x *= s; v.y *= s; v.z *= s; v.w *= s;
                } else {
                    v = *(const float4*)&hin[n * 64 + kq * 4];
                }
            }
            XsT[kq * 4 + 0][node] = v.x;
            XsT[kq * 4 + 1][node] = v.y;
            XsT[kq * 4 + 2][node] = v.z;
            XsT[kq * 4 + 3][node] = v.w;
        }
        __syncthreads();
        #pragma unroll 8
        for (int k = 0; k < 64; k++) {
            float4 xv = *(const float4*)&XsT[k][nt * 4];
            float4 wv = *(const float4*)&Ws[k][ct * 4];
            a0.x += xv.x * wv.x; a0.y += xv.x * wv.y; a0.z += xv.x * wv.z; a0.w += xv.x * wv.w;
            a1.x += xv.y * wv.x; a1.y += xv.y * wv.y; a1.z += xv.y * wv.z; a1.w += xv.y * wv.w;
            a2.x += xv.z * wv.x; a2.y += xv.z * wv.y; a2.z += xv.z * wv.z; a2.w += xv.z * wv.w;
            a3.x += xv.w * wv.x; a3.y += xv.w * wv.y; a3.z += xv.w * wv.z; a3.w += xv.w * wv.w;
        }
    }

    float4 bb = *(const float4*)&bs[ct * 4];
    float4 acc[4] = {a0, a1, a2, a3};
    #pragma unroll
    for (int i = 0; i < 4; i++) {
        int n = nb + nt * 4 + i;
        if (n >= N_NODES) break;
        float4 o;
        o.x = fmaxf(acc[i].x + bb.x, 0.f);
        o.y = fmaxf(acc[i].y + bb.y, 0.f);
        o.z = fmaxf(acc[i].z + bb.z, 0.f);
        o.w = fmaxf(acc[i].w + bb.w, 0.f);
        if (layer == 0)
            *(float4*)&g_h1[n * 64 + ct * 4] = o;
        *(float4*)&g_agg[n * 64 + ct * 4] = make_float4(0.f,0.f,0.f,0.f);
        if (layer == 1)
            atomicAdd((float4*)&g_pool[batch[n] * 64 + ct * 4], o);
    }
}

// ---------------------------------------------------------------------------
// Classifier: out[g] = (pool[g]/pcnt[g]) @ wc + bc
__global__ void k_final(const float* __restrict__ wc,
                        const float* __restrict__ bc,
                        float* __restrict__ out) {
    int g = blockIdx.x * blockDim.x + threadIdx.x;
    if (g >= NG) return;
    float inv = 1.f / fmaxf((float)g_pcnt[g], 1.f);
    float acc[NCLS];
    #pragma unroll
    for (int c = 0; c < NCLS; c++) acc[c] = bc[c];
    for (int k = 0; k < 64; k++) {
        float p = g_pool[g * 64 + k] * inv;
        #pragma unroll
        for (int c = 0; c < NCLS; c++)
            acc[c] += p * wc[k * NCLS + c];
    }
    #pragma unroll
    for (int c = 0; c < NCLS; c++) out[g * NCLS + c] = acc[c];
}

// ---------------------------------------------------------------------------
extern "C" void kernel_launch(void* const* d_in, const int* in_sizes, int n_in,
                              void* d_out, int out_size) {
    // Input order: x, edge_index, batch, [num_graphs], shape_emb, color_emb,
    //              w1l, w1r, b1, w2l, w2r, b2, wc, bc
    int o = (n_in >= 14) ? 1 : 0;   // num_graphs scalar present or not
    const int*   x     = (const int*)d_in[0];
    const int*   ei    = (const int*)d_in[1];
    const int*   batch = (const int*)d_in[2];
    const float* semb  = (const float*)d_in[3 + o];
    const float* cemb  = (const float*)d_in[4 + o];
    const float* w1l   = (const float*)d_in[5 + o];
    const float* w1r   = (const float*)d_in[6 + o];
    const float* b1    = (const float*)d_in[7 + o];
    const float* w2l   = (const float*)d_in[8 + o];
    const float* w2r   = (const float*)d_in[9 + o];
    const float* b2    = (const float*)d_in[10 + o];
    const float* wc    = (const float*)d_in[11 + o];
    const float* bc    = (const float*)d_in[12 + o];
    float* out = (float*)d_out;

    k_zero<<<(N_NODES + 255) / 256, 256>>>();
    k_embed<<<(N_NODES * 16) / 256, 256>>>(x, batch, semb, cemb);
    k_count<<<N_EDGES / 256, 256>>>(ei);
    // layer 1
    k_scatter<<<(N_EDGES * 16) / 256, 256>>>(ei, 0);
    k_update<<<(N_NODES + 63) / 64, 256>>>(w1l, w1r, b1, batch, 0);
    // layer 2
    k_scatter<<<(N_EDGES * 16) / 256, 256>>>(ei, 1);
    k_update<<<(N_NODES + 63) / 64, 256>>>(w2l, w2r, b2, batch, 1);
    // pool -> classifier
    k_final<<<(NG + 255) / 256, 256>>>(wc, bc, out);
}

// round 2
// speedup vs baseline: 1.3100x; 1.3100x over previous
#include <cuda_runtime.h>
#include <cuda_bf16.h>

#define N_NODES 100000
#define N_EDGES 1600000
#define HID 64
#define NG 512
#define NCLS 10
#define SCAN_BS 512
#define SCAN_NB ((N_NODES + SCAN_BS - 1) / SCAN_BS)   // 196

// Scratch (device globals -- no allocations allowed)
__device__ float g_h0[N_NODES * HID];
__device__ float g_h1[N_NODES * HID];
__device__ float g_agg[N_NODES * HID];
__device__ int   g_cnt[N_NODES];        // in-degree
__device__ int   g_rowptr[N_NODES + 1];
__device__ int   g_cursor[N_NODES];
__device__ int   g_eord[N_EDGES];       // src ids grouped by target
__device__ int   g_part[SCAN_NB];
__device__ float g_pool[NG * HID];
__device__ int   g_pcnt[NG];

// ---------------------------------------------------------------------------
__global__ void k_zero() {
    int i = blockIdx.x * blockDim.x + threadIdx.x;
    if (i < N_NODES) g_cnt[i] = 0;
    if (i < NG * HID) g_pool[i] = 0.f;
    if (i < NG) g_pcnt[i] = 0;
}

// ---------------------------------------------------------------------------
// Embedding lookup: h0 = concat(shape_emb[x[:,0]], color_emb[x[:,1]])
// 16 threads per node, one float4 each. Also per-graph node counts.
__global__ void k_embed(const int* __restrict__ x,
                        const int* __restrict__ batch,
                        const float* __restrict__ semb,
                        const float* __restrict__ cemb) {
    int t = blockIdx.x * blockDim.x + threadIdx.x;   // N_NODES*16 threads
    int node = t >> 4, c4 = t & 15;
    float4 v;
    if (c4 < 8) {
        int s = x[node * 2 + 0];
        v = *(const float4*)&semb[s * 32 + c4 * 4];
    } else {
        int c = x[node * 2 + 1];
        v = *(const float4*)&cemb[c * 32 + (c4 - 8) * 4];
    }
    *(float4*)&g_h0[node * 64 + c4 * 4] = v;
    if (c4 == 0) atomicAdd(&g_pcnt[batch[node]], 1);
}

// ---------------------------------------------------------------------------
// In-degree histogram
__global__ void k_count(const int* __restrict__ ei) {
    int e = blockIdx.x * blockDim.x + threadIdx.x;
    atomicAdd(&g_cnt[ei[N_EDGES + e]], 1);
}

// Block-local exclusive scan of degrees (SCAN_BS per block)
__global__ void k_scan1() {
    __shared__ int s[SCAN_BS];
    int tid = threadIdx.x;
    int i = blockIdx.x * SCAN_BS + tid;
    int v = (i < N_NODES) ? g_cnt[i] : 0;
    s[tid] = v;
    __syncthreads();
    for (int off = 1; off < SCAN_BS; off <<= 1) {
        int t = (tid >= off) ? s[tid - off] : 0;
        __syncthreads();
        s[tid] += t;
        __syncthreads();
    }
    if (i < N_NODES) g_rowptr[i] = s[tid] - v;   // local exclusive
    if (tid == SCAN_BS - 1) g_part[blockIdx.x] = s[tid];
}

// Single-warp scan of block partials
__global__ void k_scan2() {
    int lane = threadIdx.x;
    int carry = 0;
    for (int base = 0; base < SCAN_NB; base += 32) {
        int idx = base + lane;
        int orig = (idx < SCAN_NB) ? g_part[idx] : 0;
        int v = orig;
        #pragma unroll
        for (int off = 1; off < 32; off <<= 1) {
            int t = __shfl_up_sync(0xffffffffu, v, off);
            if (lane >= off) v += t;
        }
        if (idx < SCAN_NB) g_part[idx] = carry + v - orig;  // exclusive
        carry += __shfl_sync(0xffffffffu, v, 31);
    }
}

// Add block offsets; init cursors
__global__ void k_scan3() {
    int i = blockIdx.x * blockDim.x + threadIdx.x;
    if (i < N_NODES) {
        int r = g_rowptr[i] + g_part[i / SCAN_BS];
        g_rowptr[i] = r;
        g_cursor[i] = r;
    }
    if (i == 0) g_rowptr[N_NODES] = N_EDGES;
}

// Bucket edges by target: g_eord holds src indices grouped by target
__global__ void k_bucket(const int* __restrict__ ei) {
    int e = blockIdx.x * blockDim.x + threadIdx.x;
    int tgt = ei[N_EDGES + e];
    int pos = atomicAdd(&g_cursor[tgt], 1);
    g_eord[pos] = ei[e];
}

// ---------------------------------------------------------------------------
// CSR gather: agg[n] = mean over neighbors of h[src]. One warp per node,
// float2 per lane. Pre-divides by degree.
__global__ void __launch_bounds__(256) k_gather(int layer) {
    int w = (blockIdx.x * blockDim.x + threadIdx.x) >> 5;
    int lane = threadIdx.x & 31;
    if (w >= N_NODES) return;
    int start = g_rowptr[w], end = g_rowptr[w + 1];
    const float* __restrict__ h = layer ? g_h1 : g_h0;
    float2 acc = make_float2(0.f, 0.f);
    for (int base = start; base < end; base += 32) {
        int idx = (base + lane < end) ? g_eord[base + lane] : 0;
        int m = min(32, end - base);
        for (int j = 0; j < m; j++) {
            int s = __shfl_sync(0xffffffffu, idx, j);
            float2 v = *(const float2*)&h[s * 64 + lane * 2];
            acc.x += v.x;
            acc.y += v.y;
        }
    }
    float inv = 1.f / (float)max(end - start, 1);
    acc.x *= inv; acc.y *= inv;
    *(float2*)&g_agg[w * 64 + lane * 2] = acc;
}

// ---------------------------------------------------------------------------
// Node update: out = relu( agg @ wl + h @ wr + b )     (agg already mean)
// Tiled GEMM: 64 nodes x 64 cols per block, 256 threads, 4x4 micro-tiles.
__global__ void __launch_bounds__(256) k_update(
        const float* __restrict__ wl, const float* __restrict__ wr,
        const float* __restrict__ bias, const int* __restrict__ batch,
        int layer) {
    __shared__ float Ws[64][64];
    __shared__ float XsT[64][64];
    __shared__ float bs[64];

    const float* __restrict__ hin = layer ? g_h1 : g_h0;
    int t  = threadIdx.x;
    int nb = blockIdx.x * 64;
    int nt = t & 15;   // node group (4 nodes)
    int ct = t >> 4;   // col group (4 cols)

    if (t < 64) bs[t] = bias[t];

    float4 a0 = make_float4(0.f,0.f,0.f,0.f);
    float4 a1 = a0, a2 = a0, a3 = a0;

    for (int kc = 0; kc < 2; kc++) {
        __syncthreads();
        const float* w = kc ? wr : wl;
        for (int i = t; i < 1024; i += 256)
            ((float4*)&Ws[0][0])[i] = ((const float4*)w)[i];
        const float* src = kc ? hin : g_agg;
        for (int i = t; i < 1024; i += 256) {
            int node = i & 63, kq = i >> 6;
            int n = nb + node;
            float4 v = make_float4(0.f,0.f,0.f,0.f);
            if (n < N_NODES) v = *(const float4*)&src[n * 64 + kq * 4];
            XsT[kq * 4 + 0][node] = v.x;
            XsT[kq * 4 + 1][node] = v.y;
            XsT[kq * 4 + 2][node] = v.z;
            XsT[kq * 4 + 3][node] = v.w;
        }
        __syncthreads();
        #pragma unroll 8
        for (int k = 0; k < 64; k++) {
            float4 xv = *(const float4*)&XsT[k][nt * 4];
            float4 wv = *(const float4*)&Ws[k][ct * 4];
            a0.x += xv.x * wv.x; a0.y += xv.x * wv.y; a0.z += xv.x * wv.z; a0.w += xv.x * wv.w;
            a1.x += xv.y * wv.x; a1.y += xv.y * wv.y; a1.z += xv.y * wv.z; a1.w += xv.y * wv.w;
            a2.x += xv.z * wv.x; a2.y += xv.z * wv.y; a2.z += xv.z * wv.z; a2.w += xv.z * wv.w;
            a3.x += xv.w * wv.x; a3.y += xv.w * wv.y; a3.z += xv.w * wv.z; a3.w += xv.w * wv.w;
        }
    }

    float4 bb = *(const float4*)&bs[ct * 4];
    float4 acc[4] = {a0, a1, a2, a3};
    #pragma unroll
    for (int i = 0; i < 4; i++) {
        int n = nb + nt * 4 + i;
        if (n >= N_NODES) break;
        float4 o;
        o.x = fmaxf(acc[i].x + bb.x, 0.f);
        o.y = fmaxf(acc[i].y + bb.y, 0.f);
        o.z = fmaxf(acc[i].z + bb.z, 0.f);
        o.w = fmaxf(acc[i].w + bb.w, 0.f);
        if (layer == 0)
            *(float4*)&g_h1[n * 64 + ct * 4] = o;
        else
            atomicAdd((float4*)&g_pool[batch[n] * 64 + ct * 4], o);
    }
}

// ---------------------------------------------------------------------------
// Classifier: out[g] = (pool[g]/pcnt[g]) @ wc + bc
__global__ void k_final(const float* __restrict__ wc,
                        const float* __restrict__ bc,
                        float* __restrict__ out) {
    int g = blockIdx.x * blockDim.x + threadIdx.x;
    if (g >= NG) return;
    float inv = 1.f / fmaxf((float)g_pcnt[g], 1.f);
    float acc[NCLS];
    #pragma unroll
    for (int c = 0; c < NCLS; c++) acc[c] = bc[c];
    for (int k = 0; k < 64; k++) {
        float p = g_pool[g * 64 + k] * inv;
        #pragma unroll
        for (int c = 0; c < NCLS; c++)
            acc[c] += p * wc[k * NCLS + c];
    }
    #pragma unroll
    for (int c = 0; c < NCLS; c++) out[g * NCLS + c] = acc[c];
}

// ---------------------------------------------------------------------------
extern "C" void kernel_launch(void* const* d_in, const int* in_sizes, int n_in,
                              void* d_out, int out_size) {
    int o = (n_in >= 14) ? 1 : 0;   // num_graphs scalar present or not
    const int*   x     = (const int*)d_in[0];
    const int*   ei    = (const int*)d_in[1];
    const int*   batch = (const int*)d_in[2];
    const float* semb  = (const float*)d_in[3 + o];
    const float* cemb  = (const float*)d_in[4 + o];
    const float* w1l   = (const float*)d_in[5 + o];
    const float* w1r   = (const float*)d_in[6 + o];
    const float* b1    = (const float*)d_in[7 + o];
    const float* w2l   = (const float*)d_in[8 + o];
    const float* w2r   = (const float*)d_in[9 + o];
    const float* b2    = (const float*)d_in[10 + o];
    const float* wc    = (const float*)d_in[11 + o];
    const float* bc    = (const float*)d_in[12 + o];
    float* out = (float*)d_out;

    k_zero<<<(N_NODES + 255) / 256, 256>>>();
    k_embed<<<(N_NODES * 16) / 256, 256>>>(x, batch, semb, cemb);
    // CSR build (shared by both layers)
    k_count<<<N_EDGES / 256, 256>>>(ei);
    k_scan1<<<SCAN_NB, SCAN_BS>>>();
    k_scan2<<<1, 32>>>();
    k_scan3<<<(N_NODES + 255) / 256, 256>>>();
    k_bucket<<<N_EDGES / 256, 256>>>(ei);
    // layer 1
    k_gather<<<(N_NODES * 32 + 255) / 256, 256>>>(0);
    k_update<<<(N_NODES + 63) / 64, 256>>>(w1l, w1r, b1, batch, 0);
    // layer 2
    k_gather<<<(N_NODES * 32 + 255) / 256, 256>>>(1);
    k_update<<<(N_NODES + 63) / 64, 256>>>(w2l, w2r, b2, batch, 1);
    // pool -> classifier
    k_final<<<(NG + 255) / 256, 256>>>(wc, bc, out);
}

// round 5
// speedup vs baseline: 1.5990x; 1.2206x over previous
#include <cuda_runtime.h>
#include <cuda_fp16.h>
#include <cstdint>

#define N_NODES 100000
#define N_EDGES 1600000
#define HID 64
#define NG 512
#define NCLS 10
#define SCAN_BS 512
#define SCAN_NB ((N_NODES + SCAN_BS - 1) / SCAN_BS)   // 196

// ---------------- device scratch (no allocations allowed) -------------------
__device__ __half g_h0[N_NODES * HID];
__device__ __half g_h1[N_NODES * HID];
__device__ __half g_agg[N_NODES * HID];
__device__ __half g_wT[4 * 4096];   // wT[m][n*64+k] = w[k][n], fp16
__device__ int   g_cnt[N_NODES];
__device__ int   g_rowptr[N_NODES + 1];
__device__ int   g_cursor[N_NODES];
__device__ int   g_eord[N_EDGES];
__device__ int   g_part[SCAN_NB];
__device__ float g_pool[NG * HID];
__device__ int   g_pcnt[NG];

// ---------------------------------------------------------------------------
__global__ void k_zero() {
    int i = blockIdx.x * blockDim.x + threadIdx.x;
    if (i < N_NODES) g_cnt[i] = 0;
    if (i < NG * HID) g_pool[i] = 0.f;
    if (i < NG) g_pcnt[i] = 0;
}

// Embedding: h0 = concat(semb[x0], cemb[x1]) in fp16. 8 threads/node.
__global__ void k_embed(const int* __restrict__ x,
                        const int* __restrict__ batch,
                        const float* __restrict__ semb,
                        const float* __restrict__ cemb) {
    int t = blockIdx.x * blockDim.x + threadIdx.x;   // N_NODES*8
    int node = t >> 3, j = t & 7;
    const float4* src;
    if (j < 4) {
        int s = x[node * 2 + 0];
        src = (const float4*)&semb[s * 32 + j * 8];
    } else {
        int c = x[node * 2 + 1];
        src = (const float4*)&cemb[c * 32 + (j - 4) * 8];
    }
    float4 a = src[0], b = src[1];
    __half2 p0 = __floats2half2_rn(a.x, a.y);
    __half2 p1 = __floats2half2_rn(a.z, a.w);
    __half2 p2 = __floats2half2_rn(b.x, b.y);
    __half2 p3 = __floats2half2_rn(b.z, b.w);
    uint4 o = make_uint4(*(uint32_t*)&p0, *(uint32_t*)&p1,
                         *(uint32_t*)&p2, *(uint32_t*)&p3);
    *(uint4*)&g_h0[node * 64 + j * 8] = o;
    if (j == 0) atomicAdd(&g_pcnt[batch[node]], 1);
}

// Transpose weights to k-major fp16: wT[n][k] = w[k][n]
__global__ void k_prepw(const float* __restrict__ w0,
                        const float* __restrict__ w1,
                        const float* __restrict__ w2,
                        const float* __restrict__ w3) {
    int id = blockIdx.x * blockDim.x + threadIdx.x;   // 16384
    int m = id >> 12, r = id & 4095;
    int n = r >> 6, k = r & 63;
    const float* w = (m == 0) ? w0 : (m == 1) ? w1 : (m == 2) ? w2 : w3;
    g_wT[m * 4096 + n * 64 + k] = __float2half_rn(w[k * 64 + n]);
}

// In-degree histogram
__global__ void k_count(const int* __restrict__ ei) {
    int e = blockIdx.x * blockDim.x + threadIdx.x;
    atomicAdd(&g_cnt[ei[N_EDGES + e]], 1);
}

__global__ void k_scan1() {
    __shared__ int s[SCAN_BS];
    int tid = threadIdx.x;
    int i = blockIdx.x * SCAN_BS + tid;
    int v = (i < N_NODES) ? g_cnt[i] : 0;
    s[tid] = v;
    __syncthreads();
    for (int off = 1; off < SCAN_BS; off <<= 1) {
        int t = (tid >= off) ? s[tid - off] : 0;
        __syncthreads();
        s[tid] += t;
        __syncthreads();
    }
    if (i < N_NODES) g_rowptr[i] = s[tid] - v;
    if (tid == SCAN_BS - 1) g_part[blockIdx.x] = s[tid];
}

__global__ void k_scan2() {
    int lane = threadIdx.x;
    int carry = 0;
    for (int base = 0; base < SCAN_NB; base += 32) {
        int idx = base + lane;
        int orig = (idx < SCAN_NB) ? g_part[idx] : 0;
        int v = orig;
        #pragma unroll
        for (int off = 1; off < 32; off <<= 1) {
            int t = __shfl_up_sync(0xffffffffu, v, off);
            if (lane >= off) v += t;
        }
        if (idx < SCAN_NB) g_part[idx] = carry + v - orig;
        carry += __shfl_sync(0xffffffffu, v, 31);
    }
}

__global__ void k_scan3() {
    int i = blockIdx.x * blockDim.x + threadIdx.x;
    if (i < N_NODES) {
        int r = g_rowptr[i] + g_part[i / SCAN_BS];
        g_rowptr[i] = r;
        g_cursor[i] = r;
    }
    if (i == 0) g_rowptr[N_NODES] = N_EDGES;
}

__global__ void k_bucket(const int* __restrict__ ei) {
    int e = blockIdx.x * blockDim.x + threadIdx.x;
    int tgt = ei[N_EDGES + e];
    int pos = atomicAdd(&g_cursor[tgt], 1);
    g_eord[pos] = ei[e];
}

// ---------------------------------------------------------------------------
// CSR gather (fp16): agg[n] = mean_{s in N(n)} h[s]. One warp/node.
// fp32 accumulation.
__global__ void __launch_bounds__(256) k_gather(int layer) {
    int w = (blockIdx.x * blockDim.x + threadIdx.x) >> 5;
    int lane = threadIdx.x & 31;
    if (w >= N_NODES) return;
    int start = g_rowptr[w], end = g_rowptr[w + 1];
    const __half* __restrict__ h = layer ? g_h1 : g_h0;
    float2 acc = make_float2(0.f, 0.f);
    for (int base = start; base < end; base += 32) {
        int idx = (base + lane < end) ? g_eord[base + lane] : 0;
        int m = min(32, end - base);
        for (int j = 0; j < m; j++) {
            int s = __shfl_sync(0xffffffffu, idx, j);
            __half2 v = *(const __half2*)&h[s * 64 + lane * 2];
            float2 f = __half22float2(v);
            acc.x += f.x;
            acc.y += f.y;
        }
    }
    float inv = 1.f / (float)max(end - start, 1);
    acc.x *= inv; acc.y *= inv;
    __half2 o = __floats2half2_rn(acc.x, acc.y);
    *(__half2*)&g_agg[w * 64 + lane * 2] = o;
}

// ---------------------------------------------------------------------------
// HMMA node update: out = relu(agg @ wl + h @ wr + b)
// mma.sync.m16n8k16 f16 -> f32. 256 threads = 8 warps, 128 nodes/block.
// A and B fragments loaded directly from gmem (k-major, contiguous b32 per
// fragment register). No smem tiles.
__global__ void __launch_bounds__(256) k_upd(const float* __restrict__ bias,
                                             const int* __restrict__ batch,
                                             int layer) {
    __shared__ float sbias[64];
    int tid = threadIdx.x;
    int wid = tid >> 5, lane = tid & 31;
    if (tid < 64) sbias[tid] = bias[tid];
    __syncthreads();

    int m0 = blockIdx.x * 128 + wid * 16;
    int qp = (lane & 3) * 2;       // k-pair offset within 16
    int gi = lane >> 2;            // group index 0..7
    int r0 = m0 + gi;
    int r1 = r0 + 8;
    bool v0 = r0 < N_NODES, v1 = r1 < N_NODES;

    float acc[8][4];
    #pragma unroll
    for (int t = 0; t < 8; t++)
        #pragma unroll
        for (int i = 0; i < 4; i++) acc[t][i] = 0.f;

    const __half* __restrict__ hin = layer ? g_h1 : g_h0;

    #pragma unroll
    for (int kc = 0; kc < 2; kc++) {
        const __half* __restrict__ X = kc ? hin : g_agg;
        const __half* __restrict__ W = &g_wT[(layer * 2 + kc) * 4096];
        #pragma unroll
        for (int ks = 0; ks < 4; ks++) {
            int kb = ks * 16;
            uint32_t a0 = 0, a1 = 0, a2 = 0, a3 = 0;
            if (v0) {
                a0 = *(const uint32_t*)&X[(size_t)r0 * 64 + kb + qp];
                a2 = *(const uint32_t*)&X[(size_t)r0 * 64 + kb + qp + 8];
            }
            if (v1) {
                a1 = *(const uint32_t*)&X[(size_t)r1 * 64 + kb + qp];
                a3 = *(const uint32_t*)&X[(size_t)r1 * 64 + kb + qp + 8];
            }
            #pragma unroll
            for (int t = 0; t < 8; t++) {
                int n = t * 8 + gi;
                uint32_t b0 = *(const uint32_t*)&W[n * 64 + kb + qp];
                uint32_t b1 = *(const uint32_t*)&W[n * 64 + kb + qp + 8];
                asm volatile(
                    "mma.sync.aligned.m16n8k16.row.col.f32.f16.f16.f32 "
                    "{%0,%1,%2,%3}, {%4,%5,%6,%7}, {%8,%9}, {%0,%1,%2,%3};"
                    : "+f"(acc[t][0]), "+f"(acc[t][1]),
                      "+f"(acc[t][2]), "+f"(acc[t][3])
                    : "r"(a0), "r"(a1), "r"(a2), "r"(a3), "r"(b0), "r"(b1));
            }
        }
    }

    // epilogue: bias + relu, then store (layer 0) or pool (layer 1)
    int b0g = v0 ? batch[r0] : 0;
    int b1g = v1 ? batch[r1] : 0;
    #pragma unroll
    for (int t = 0; t < 8; t++) {
        int ct = t * 8 + qp;
        float bx = sbias[ct], by = sbias[ct + 1];
        float o0 = fmaxf(acc[t][0] + bx, 0.f);
        float o1 = fmaxf(acc[t][1] + by, 0.f);
        float o2 = fmaxf(acc[t][2] + bx, 0.f);
        float o3 = fmaxf(acc[t][3] + by, 0.f);
        if (layer == 0) {
            if (v0) {
                __half2 p = __floats2half2_rn(o0, o1);
                *(__half2*)&g_h1[(size_t)r0 * 64 + ct] = p;
            }
            if (v1) {
                __half2 p = __floats2half2_rn(o2, o3);
                *(__half2*)&g_h1[(size_t)r1 * 64 + ct] = p;
            }
        } else {
            if (v0) atomicAdd((float2*)&g_pool[b0g * 64 + ct],
                              make_float2(o0, o1));
            if (v1) atomicAdd((float2*)&g_pool[b1g * 64 + ct],
                              make_float2(o2, o3));
        }
    }
}

// ---------------------------------------------------------------------------
__global__ void k_final(const float* __restrict__ wc,
                        const float* __restrict__ bc,
                        float* __restrict__ out) {
    int g = blockIdx.x * blockDim.x + threadIdx.x;
    if (g >= NG) return;
    float inv = 1.f / fmaxf((float)g_pcnt[g], 1.f);
    float acc[NCLS];
    #pragma unroll
    for (int c = 0; c < NCLS; c++) acc[c] = bc[c];
    for (int k = 0; k < 64; k++) {
        float p = g_pool[g * 64 + k] * inv;
        #pragma unroll
        for (int c = 0; c < NCLS; c++)
            acc[c] += p * wc[k * NCLS + c];
    }
    #pragma unroll
    for (int c = 0; c < NCLS; c++) out[g * NCLS + c] = acc[c];
}

// ---------------------------------------------------------------------------
extern "C" void kernel_launch(void* const* d_in, const int* in_sizes, int n_in,
                              void* d_out, int out_size) {
    int o = (n_in >= 14) ? 1 : 0;
    const int*   x     = (const int*)d_in[0];
    const int*   ei    = (const int*)d_in[1];
    const int*   batch = (const int*)d_in[2];
    const float* semb  = (const float*)d_in[3 + o];
    const float* cemb  = (const float*)d_in[4 + o];
    const float* w1l   = (const float*)d_in[5 + o];
    const float* w1r   = (const float*)d_in[6 + o];
    const float* b1    = (const float*)d_in[7 + o];
    const float* w2l   = (const float*)d_in[8 + o];
    const float* w2r   = (const float*)d_in[9 + o];
    const float* b2    = (const float*)d_in[10 + o];
    const float* wc    = (const float*)d_in[11 + o];
    const float* bc    = (const float*)d_in[12 + o];
    float* out = (float*)d_out;

    k_zero<<<(N_NODES + 255) / 256, 256>>>();
    k_embed<<<(N_NODES * 8) / 256, 256>>>(x, batch, semb, cemb);
    k_prepw<<<64, 256>>>(w1l, w1r, w2l, w2r);
    // CSR build (shared by both layers)
    k_count<<<N_EDGES / 256, 256>>>(ei);
    k_scan1<<<SCAN_NB, SCAN_BS>>>();
    k_scan2<<<1, 32>>>();
    k_scan3<<<(N_NODES + 255) / 256, 256>>>();
    k_bucket<<<N_EDGES / 256, 256>>>(ei);
    // layer 1
    k_gather<<<(N_NODES * 32 + 255) / 256, 256>>>(0);
    k_upd<<<(N_NODES + 127) / 128, 256>>>(b1, batch, 0);
    // layer 2
    k_gather<<<(N_NODES * 32 + 255) / 256, 256>>>(1);
    k_upd<<<(N_NODES + 127) / 128, 256>>>(b2, batch, 1);
    // pool -> classifier
    k_final<<<(NG + 255) / 256, 256>>>(wc, bc, out);
}